// round 8
// baseline (speedup 1.0000x reference)
#include <cuda_runtime.h>
#include <cuda_fp16.h>
#include <cuda_fp8.h>
#include <cstdint>

// Problem constants
#define N_TOK   4096
#define D_MODEL 1024
#define D_HID   32768
#define TOPK    128
#define EPS     1e-5f
#define CAND_MAX 512
#define MARGIN  0.04f
#define NBINS   8192
#define BSCALE  8192.0f

// GEMM tiling (fp8: 128B row = 128 elements of K)
#define TM   128
#define TN   128
#define TKC  128                         // k-elements per chunk (128B rows)
#define NCHUNK (D_MODEL / TKC)           // 8
#define STAGE_BYTES 32768                // a8(16K) + b8(16K)
#define GEMM_SMEM (2 * STAGE_BYTES)      // 64 KB

// Rescue tiling
#define RTILE 64
#define RPAD  65
#define RES_SMEM ((D_MODEL + CAND_MAX * RPAD + CAND_MAX + CAND_MAX) * 4)

// ---------------- scratch (device globals; no allocs allowed) ----------------
__device__ __nv_fp8_e4m3 g_a8[(size_t)N_TOK * D_MODEL];    // xn e4m3
__device__ float  g_xn[(size_t)N_TOK * D_MODEL];           // xn fp32 (rescue)
__device__ __nv_fp8_e4m3 g_b8[(size_t)D_HID * D_MODEL];    // (8192*w_enc)^T e4m3
__device__ float  g_bt[(size_t)D_HID * D_MODEL];           // w_enc^T fp32 (rescue)
__device__ __half g_preh[(size_t)N_TOK * D_HID];           // 256 MB approx pre-acts
__device__ float g_mu[N_TOK];
__device__ float g_sd[N_TOK];
__device__ int   g_ci[(size_t)N_TOK * CAND_MAX];           // candidate indices
__device__ int   g_cn[N_TOK];                              // candidate counts
__device__ float g_tv[(size_t)N_TOK * TOPK];
__device__ int   g_ti[(size_t)N_TOK * TOPK];

// ---------------- PTX helpers -------------------------------------------------
__device__ __forceinline__ uint32_t smem_u32(const void* p) {
    uint32_t a;
    asm("{ .reg .u64 t; cvta.to.shared.u64 t, %1; cvt.u32.u64 %0, t; }" : "=r"(a) : "l"(p));
    return a;
}
__device__ __forceinline__ void cp16(uint32_t dst, const void* src) {
    asm volatile("cp.async.cg.shared.global [%0], [%1], 16;" :: "r"(dst), "l"(src) : "memory");
}
#define CP_COMMIT()   asm volatile("cp.async.commit_group;" ::: "memory")
#define CP_WAIT(n)    asm volatile("cp.async.wait_group %0;" :: "n"(n) : "memory")

#define LDSM4(R0, R1, R2, R3, A)                                                  \
    asm volatile("ldmatrix.sync.aligned.m8n8.x4.shared.b16 {%0,%1,%2,%3}, [%4];"  \
        : "=r"(R0), "=r"(R1), "=r"(R2), "=r"(R3) : "r"(A))

// fp8 e4m3 MMA: m16n8k32, fp32 accumulate. Fragment byte-layout is identical
// to fp16 m16n8k16 (each b16 lane-slot = 2 e4m3), so ldmatrix code is reused.
#define MMAFP8(D, A, B0, B1)                                                      \
    asm volatile("mma.sync.aligned.m16n8k32.row.col.f32.e4m3.e4m3.f32 "           \
        "{%0,%1,%2,%3}, {%4,%5,%6,%7}, {%8,%9}, {%0,%1,%2,%3};"                   \
        : "+f"((D)[0]), "+f"((D)[1]), "+f"((D)[2]), "+f"((D)[3])                   \
        : "r"((A)[0]), "r"((A)[1]), "r"((A)[2]), "r"((A)[3]), "r"(B0), "r"(B1))

// ---------------- LayerNorm ----------------------------------------------------
__device__ __forceinline__ float block_reduce_sum256(float v, float* red) {
    #pragma unroll
    for (int o = 16; o > 0; o >>= 1) v += __shfl_xor_sync(0xffffffffu, v, o);
    int w = threadIdx.x >> 5;
    if ((threadIdx.x & 31) == 0) red[w] = v;
    __syncthreads();
    float r = (threadIdx.x < 8) ? red[threadIdx.x] : 0.f;
    if (threadIdx.x < 32) {
        #pragma unroll
        for (int o = 4; o > 0; o >>= 1) r += __shfl_xor_sync(0xffffffffu, r, o);
        if (threadIdx.x == 0) red[0] = r;
    }
    __syncthreads();
    float out = red[0];
    __syncthreads();
    return out;
}

__global__ __launch_bounds__(256) void ln_kernel(const float* __restrict__ x,
                                                 const float* __restrict__ b_pre) {
    __shared__ float sx[D_MODEL];
    __shared__ float red[32];
    const int row = blockIdx.x;
    const int t = threadIdx.x;
    const float* xr = x + (size_t)row * D_MODEL;

    float sum = 0.f;
    #pragma unroll
    for (int q = 0; q < 4; q++) { float f = xr[t + q * 256]; sx[t + q * 256] = f; sum += f; }
    float m = block_reduce_sum256(sum, red) * (1.0f / D_MODEL);

    float sq = 0.f;
    #pragma unroll
    for (int q = 0; q < 4; q++) { float c = sx[t + q * 256] - m; sq += c * c; }
    float sd = sqrtf(block_reduce_sum256(sq, red) * (1.0f / (D_MODEL - 1)));
    float inv = 1.0f / (sd + EPS);

    #pragma unroll
    for (int q = 0; q < 4; q++) {
        int col = t + q * 256;
        float v = (sx[col] - m) * inv - b_pre[col];
        size_t idx = (size_t)row * D_MODEL + col;
        g_xn[idx] = v;
        g_a8[idx] = __nv_fp8_e4m3(v);
    }
    if (t == 0) { g_mu[row] = m; g_sd[row] = sd; }
}

// ---------------- transpose: w_enc -> [D_HID, D_MODEL] fp32 + e4m3(x8192) -----
__global__ __launch_bounds__(256) void transpose_split(const float* __restrict__ w) {
    __shared__ float tile[32][33];
    const int n0 = blockIdx.x * 32, k0 = blockIdx.y * 32;
    const int tx = threadIdx.x, ty = threadIdx.y;
    #pragma unroll
    for (int i = 0; i < 32; i += 8)
        tile[ty + i][tx] = w[(size_t)(k0 + ty + i) * D_HID + n0 + tx];
    __syncthreads();
    #pragma unroll
    for (int i = 0; i < 32; i += 8) {
        float v = tile[tx][ty + i];
        size_t idx = (size_t)(n0 + ty + i) * D_MODEL + k0 + tx;
        g_bt[idx] = v;
        g_b8[idx] = __nv_fp8_e4m3(v * BSCALE);   // scale into e4m3 normal range
    }
}

// ---------------- fp8 MMA GEMM (approx pre-acts) ------------------------------
// A tiles [128 rows x 128 B], B tiles [128 rows x 128 B], 16B-chunk XOR swizzle.
__device__ __forceinline__ void load_chunk(uint32_t stage, int bm, int bn, int k0, int t) {
    #pragma unroll
    for (int i = 0; i < 4; i++) {
        int g = t + i * 256;                // 0..1023
        int row = g >> 3, ch = g & 7;
        uint32_t dst = stage + (uint32_t)row * 128 + (uint32_t)((ch ^ (row & 7)) * 16);
        cp16(dst,         (const char*)g_a8 + (size_t)(bm + row) * D_MODEL + k0 + ch * 16);
        cp16(dst + 16384, (const char*)g_b8 + (size_t)(bn + row) * D_MODEL + k0 + ch * 16);
    }
}

__global__ __launch_bounds__(256, 2) void enc_gemm_mma(const float* __restrict__ bias) {
    extern __shared__ __align__(1024) char smem[];
    const uint32_t sb = smem_u32(smem);
    const int t = threadIdx.x;
    const int wid = t >> 5, lane = t & 31;
    const int wm = wid >> 1, wn = wid & 1;      // 4x2 warps, warp tile 32x64
    const int bm = blockIdx.x * TM;
    const int bn = blockIdx.y * TN;

    float acc[2][8][4];
    #pragma unroll
    for (int i = 0; i < 2; i++)
        #pragma unroll
        for (int j = 0; j < 8; j++)
            #pragma unroll
            for (int q = 0; q < 4; q++) acc[i][j][q] = 0.f;

    const int laneA = lane & 15;
    const int hiA   = lane >> 4;
    const int rBoff = (lane & 7) + ((lane >> 4) << 3);
    const int hiB   = (lane >> 3) & 1;

    load_chunk(sb, bm, bn, 0, t);
    CP_COMMIT();

    for (int c = 0; c < NCHUNK; c++) {
        if (c + 1 < NCHUNK) {
            load_chunk(sb + (uint32_t)((c + 1) & 1) * STAGE_BYTES, bm, bn, (c + 1) * TKC, t);
            CP_COMMIT();
            CP_WAIT(1);
        } else {
            CP_WAIT(0);
        }
        __syncthreads();

        const uint32_t base = sb + (uint32_t)(c & 1) * STAGE_BYTES;
        const uint32_t Ah = base, Bh = base + 16384;

        #pragma unroll
        for (int ks = 0; ks < 4; ks++) {       // each ks = 32 fp8 k-elements = 32 B
            const int c0 = ks * 2;
            uint32_t aH[2][4], bH[8][2];
            #pragma unroll
            for (int tm = 0; tm < 2; tm++) {
                int r = wm * 32 + tm * 16 + laneA;
                uint32_t off = (uint32_t)r * 128 + (uint32_t)((((c0 + hiA) ^ (r & 7))) * 16);
                LDSM4(aH[tm][0], aH[tm][1], aH[tm][2], aH[tm][3], Ah + off);
            }
            #pragma unroll
            for (int tp = 0; tp < 4; tp++) {
                int r = wn * 64 + tp * 16 + rBoff;
                uint32_t off = (uint32_t)r * 128 + (uint32_t)((((c0 + hiB) ^ (r & 7))) * 16);
                LDSM4(bH[2*tp][0], bH[2*tp][1], bH[2*tp+1][0], bH[2*tp+1][1], Bh + off);
            }
            #pragma unroll
            for (int tm = 0; tm < 2; tm++)
                #pragma unroll
                for (int tn = 0; tn < 8; tn++)
                    MMAFP8(acc[tm][tn], aH[tm], bH[tn][0], bH[tn][1]);
        }
        __syncthreads();
    }

    // epilogue: unscale (B was x8192), add bias, store fp16
    const float invS = 1.0f / BSCALE;
    const int gid = lane >> 2, tig = lane & 3;
    #pragma unroll
    for (int tm = 0; tm < 2; tm++) {
        const int r0 = bm + wm * 32 + tm * 16 + gid;
        #pragma unroll
        for (int tn = 0; tn < 8; tn++) {
            const int col = bn + wn * 64 + tn * 8 + tig * 2;
            const float b0 = __ldg(&bias[col]);
            const float b1 = __ldg(&bias[col + 1]);
            __half2 h0 = __floats2half2_rn(acc[tm][tn][0] * invS + b0,
                                           acc[tm][tn][1] * invS + b1);
            __half2 h1 = __floats2half2_rn(acc[tm][tn][2] * invS + b0,
                                           acc[tm][tn][3] * invS + b1);
            *reinterpret_cast<__half2*>(&g_preh[(size_t)r0 * D_HID + col]) = h0;
            *reinterpret_cast<__half2*>(&g_preh[(size_t)(r0 + 8) * D_HID + col]) = h1;
        }
    }
}

// ---------------- topk: fp16-key histogram select + candidate collection ------
// 8192 bins = monotonic key >> 3 (7 mantissa bits kept -> bin width ~0.8% rel).
__device__ __forceinline__ int bin_of_half_bits(uint32_t h) {
    uint32_t k = (h & 0x8000u) ? ((~h) & 0xFFFFu) : (h | 0x8000u);
    return (int)(k >> 3);
}

__global__ __launch_bounds__(256) void topk_kernel() {
    __shared__ int hist[NBINS];            // 32 KB
    __shared__ int segs[256];
    __shared__ int warpTot[8];
    __shared__ float s_thrBase;
    __shared__ int s_cnt;

    const int row = blockIdx.x;
    const int t = threadIdx.x;
    const int lane = t & 31, wid = t >> 5;
    const uint4* p4 = reinterpret_cast<const uint4*>(g_preh + (size_t)row * D_HID);

    #pragma unroll
    for (int i = 0; i < NBINS / 256; i++) hist[t + i * 256] = 0;
    __syncthreads();

    // pass 1: histogram (8 halfs per uint4)
    #pragma unroll
    for (int i = 0; i < D_HID / 8 / 256; i++) {
        uint4 v = p4[t + i * 256];
        atomicAdd(&hist[bin_of_half_bits(v.x & 0xFFFFu)], 1);
        atomicAdd(&hist[bin_of_half_bits(v.x >> 16)], 1);
        atomicAdd(&hist[bin_of_half_bits(v.y & 0xFFFFu)], 1);
        atomicAdd(&hist[bin_of_half_bits(v.y >> 16)], 1);
        atomicAdd(&hist[bin_of_half_bits(v.z & 0xFFFFu)], 1);
        atomicAdd(&hist[bin_of_half_bits(v.z >> 16)], 1);
        atomicAdd(&hist[bin_of_half_bits(v.w & 0xFFFFu)], 1);
        atomicAdd(&hist[bin_of_half_bits(v.w >> 16)], 1);
    }
    __syncthreads();

    // suffix-count crossing: segment = 32 bins per thread
    int seg = 0;
    #pragma unroll
    for (int k = 0; k < 32; k++) seg += hist[t * 32 + k];
    segs[t] = seg;
    int wsum = seg;
    #pragma unroll
    for (int o = 16; o > 0; o >>= 1) wsum += __shfl_xor_sync(0xffffffffu, wsum, o);
    if (lane == 0) warpTot[wid] = wsum;
    __syncthreads();

    if (t == 0) {
        int cum = 0, w = 7;
        for (; w > 0; w--) { if (cum + warpTot[w] >= TOPK) break; cum += warpTot[w]; }
        int s = w * 32 + 31;
        for (; s > w * 32; s--) { if (cum + segs[s] >= TOPK) break; cum += segs[s]; }
        int b = s * 32 + 31;
        for (; b > s * 32; b--) { if (cum + hist[b] >= TOPK) break; cum += hist[b]; }
        uint32_t keyLo = (uint32_t)b << 3;   // lower edge of crossing bin
        uint32_t hbits = (keyLo & 0x8000u) ? (keyLo & 0x7FFFu) : ((~keyLo) & 0xFFFFu);
        __half_raw hr; hr.x = (unsigned short)hbits;
        s_thrBase = __half2float(__half(hr));
    }
    __syncthreads();

    // pass 2: collect candidates >= thrBase - margin (halve margin on overflow)
    const __half* p = g_preh + (size_t)row * D_HID;
    float margin = MARGIN;
    for (int attempt = 0; attempt < 3; attempt++) {
        if (t == 0) s_cnt = 0;
        __syncthreads();
        const float thr = s_thrBase - margin;
        for (int i = t; i < D_HID; i += 256) {
            if (__half2float(p[i]) >= thr) {
                int pos = atomicAdd(&s_cnt, 1);
                if (pos < CAND_MAX) g_ci[(size_t)row * CAND_MAX + pos] = i;
            }
        }
        __syncthreads();
        if (s_cnt <= CAND_MAX) break;
        margin *= 0.5f;
        __syncthreads();
    }
    if (t == 0) g_cn[row] = (s_cnt < CAND_MAX) ? s_cnt : CAND_MAX;
}

// ---------------- rescue: exact fp32 dots (R1-identical order) + top-128 ------
__global__ __launch_bounds__(512, 1) void rescue_kernel(const float* __restrict__ b_enc) {
    extern __shared__ float dyn[];
    float* sx = dyn;                                   // [D_MODEL]
    float* sw = dyn + D_MODEL;                         // [CAND_MAX][RPAD]
    float* sv = sw + CAND_MAX * RPAD;                  // [CAND_MAX]
    int*   si = (int*)(sv + CAND_MAX);                 // [CAND_MAX]

    const int row = blockIdx.x;
    const int t = threadIdx.x;

    #pragma unroll
    for (int q = 0; q < 2; q++)
        sx[t + q * 512] = g_xn[(size_t)row * D_MODEL + t + q * 512];
    si[t] = (t < g_cn[row]) ? g_ci[(size_t)row * CAND_MAX + t] : 0x7FFFFFFF;
    __syncthreads();
    const int C = g_cn[row];
    const int myIdx = si[t];

    float acc = 0.f;
    for (int k0 = 0; k0 < D_MODEL; k0 += RTILE) {
        // coalesced stage: 16 threads x float4 per candidate row segment
        const int q = t & 15;                // 16 float4 = 64 floats
        #pragma unroll
        for (int pass = 0; pass < CAND_MAX / 32; pass++) {
            const int c = pass * 32 + (t >> 4);
            if (c < C) {
                const float4 v = *reinterpret_cast<const float4*>(
                    g_bt + (size_t)si[c] * D_MODEL + k0 + q * 4);
                float* dst = sw + c * RPAD + q * 4;
                dst[0] = v.x; dst[1] = v.y; dst[2] = v.z; dst[3] = v.w;
            }
        }
        __syncthreads();
        if (t < C) {
            const float* wrow = sw + t * RPAD;
            #pragma unroll
            for (int kk = 0; kk < RTILE; kk++)
                acc = fmaf(sx[k0 + kk], wrow[kk], acc);   // strict sequential chain
        }
        __syncthreads();
    }

    if (t < C) {
        sv[t] = acc + __ldg(&b_enc[myIdx]);
    } else {
        sv[t] = -__int_as_float(0x7F800000);   // -inf
    }
    __syncthreads();

    // bitonic sort 512: val desc, idx asc (jax tie order)
    #pragma unroll 1
    for (int k = 2; k <= CAND_MAX; k <<= 1) {
        #pragma unroll 1
        for (int j = k >> 1; j > 0; j >>= 1) {
            const int ixj = t ^ j;
            if (ixj > t) {
                float v0 = sv[t], v1 = sv[ixj];
                int i0 = si[t], i1 = si[ixj];
                bool firstWins = (v0 > v1) || (v0 == v1 && i0 < i1);
                if (((t & k) == 0) != firstWins) {
                    sv[t] = v1; sv[ixj] = v0;
                    si[t] = i1; si[ixj] = i0;
                }
            }
            __syncthreads();
        }
    }

    if (t < TOPK) {
        g_tv[(size_t)row * TOPK + t] = fmaxf(sv[t], 0.0f);
        g_ti[(size_t)row * TOPK + t] = si[t];
    }
}

// ---------------- sparse decode + de-normalize -------------------------------
__global__ __launch_bounds__(256) void decode_kernel(const float* __restrict__ w_dec,
                                                     const float* __restrict__ b_pre,
                                                     float* __restrict__ out) {
    __shared__ float sval[TOPK];
    __shared__ int   sidx[TOPK];
    const int row = blockIdx.x;
    const int t = threadIdx.x;
    if (t < TOPK) {
        sval[t] = g_tv[(size_t)row * TOPK + t];
        sidx[t] = g_ti[(size_t)row * TOPK + t];
    }
    __syncthreads();

    float acc0 = 0.f, acc1 = 0.f, acc2 = 0.f, acc3 = 0.f;
    #pragma unroll 4
    for (int j = 0; j < TOPK; j++) {
        const float v = sval[j];
        const float* wr = w_dec + (size_t)sidx[j] * D_MODEL;
        acc0 += v * __ldg(&wr[t]);
        acc1 += v * __ldg(&wr[t + 256]);
        acc2 += v * __ldg(&wr[t + 512]);
        acc3 += v * __ldg(&wr[t + 768]);
    }
    const float m = g_mu[row], s = g_sd[row];
    float* o = out + (size_t)row * D_MODEL;
    o[t]       = (acc0 + b_pre[t])       * s + m;
    o[t + 256] = (acc1 + b_pre[t + 256]) * s + m;
    o[t + 512] = (acc2 + b_pre[t + 512]) * s + m;
    o[t + 768] = (acc3 + b_pre[t + 768]) * s + m;
}

// ---------------- launch ------------------------------------------------------
extern "C" void kernel_launch(void* const* d_in, const int* in_sizes, int n_in,
                              void* d_out, int out_size) {
    const float* x     = (const float*)d_in[0];
    const float* w_enc = (const float*)d_in[1];
    const float* w_dec = (const float*)d_in[2];
    const float* b_enc = (const float*)d_in[3];
    const float* b_pre = (const float*)d_in[4];
    float* out = (float*)d_out;

    // 1. LayerNorm (fp32 out + e4m3 copy)
    ln_kernel<<<N_TOK, 256>>>(x, b_pre);

    // 2. Transpose w_enc -> fp32 + e4m3(x8192) [D_HID, D_MODEL]
    dim3 tg(D_HID / 32, D_MODEL / 32);
    transpose_split<<<tg, dim3(32, 8)>>>(w_enc);

    // 3. Approximate fp8 MMA encoder GEMM (m16n8k32, fp16 output)
    cudaFuncSetAttribute(enc_gemm_mma, cudaFuncAttributeMaxDynamicSharedMemorySize, GEMM_SMEM);
    dim3 ggrid(N_TOK / TM, D_HID / TN);
    enc_gemm_mma<<<ggrid, 256, GEMM_SMEM>>>(b_enc);

    // 4. Histogram-select approx top-128 + margin candidate collection
    topk_kernel<<<N_TOK, 256>>>();

    // 5. Rescue: R1-identical sequential fp32 dots, smem-staged coalesced loads
    cudaFuncSetAttribute(rescue_kernel, cudaFuncAttributeMaxDynamicSharedMemorySize, RES_SMEM);
    rescue_kernel<<<N_TOK, 512, RES_SMEM>>>(b_enc);

    // 6. Sparse decode + un-normalize
    decode_kernel<<<N_TOK, 256>>>(w_dec, b_pre, out);
}

// round 9
// speedup vs baseline: 2.3126x; 2.3126x over previous
#include <cuda_runtime.h>
#include <cuda_fp16.h>
#include <cstdint>

// Problem constants
#define N_TOK   4096
#define D_MODEL 1024
#define D_HID   32768
#define TOPK    128
#define EPS     1e-5f
#define CAND_MAX 256
#define MARGIN  4e-3f
#define NBINS   4096

// GEMM tiling
#define TM   128
#define TN   128
#define TKC  64                          // k-halfs per chunk
#define NCHUNK (D_MODEL / TKC)           // 16
#define TILE_BYTES 16384                 // one packed 128x64 fp16 tile
#define STAGE_BYTES 32768                // A tile + B tile
#define GEMM_SMEM (2 * STAGE_BYTES)      // 64 KB

// Rescue tiling
#define RTILE 64
#define RPAD  65
#define RES_SMEM ((D_MODEL + CAND_MAX * RPAD + CAND_MAX + CAND_MAX) * 4)

// ---------------- scratch (device globals; no allocs allowed) ----------------
__device__ float  g_xn[(size_t)N_TOK * D_MODEL];           // xn fp32 (rescue + packA src)
__device__ float  g_bt[(size_t)D_HID * D_MODEL];           // w_enc^T fp32 (rescue + packB src)
// packed, pre-swizzled fp16 tiles: [tileIdx][16 KB], tileIdx = blk*16 + chunk
__device__ __align__(128) __half g_ap[(size_t)N_TOK * D_MODEL];
__device__ __align__(128) __half g_bp[(size_t)D_HID * D_MODEL];
__device__ __half g_preh[(size_t)N_TOK * D_HID];           // 256 MB approx pre-acts
__device__ float g_mu[N_TOK];
__device__ float g_sd[N_TOK];
__device__ int   g_ci[(size_t)N_TOK * CAND_MAX];
__device__ int   g_cn[N_TOK];
__device__ float g_tv[(size_t)N_TOK * TOPK];
__device__ int   g_ti[(size_t)N_TOK * TOPK];

// ---------------- PTX helpers -------------------------------------------------
__device__ __forceinline__ uint32_t smem_u32(const void* p) {
    uint32_t a;
    asm("{ .reg .u64 t; cvta.to.shared.u64 t, %1; cvt.u32.u64 %0, t; }" : "=r"(a) : "l"(p));
    return a;
}
#define MBAR_INIT(a, n) asm volatile("mbarrier.init.shared.b64 [%0], %1;" :: "r"(a), "r"(n) : "memory")
#define MBAR_EXPECT(a, bytes) \
    asm volatile("mbarrier.arrive.expect_tx.shared.b64 _, [%0], %1;" :: "r"(a), "r"(bytes) : "memory")
#define MBAR_WAIT(a, ph) do {                                                          \
    uint32_t _m = (a), _p = (ph);                                                      \
    asm volatile("{\n\t.reg .pred P;\n\tWL_%=:\n\t"                                    \
        "mbarrier.try_wait.parity.acquire.cta.shared::cta.b64 P, [%0], %1, 0x989680;\n\t" \
        "@P bra.uni WD_%=;\n\tbra.uni WL_%=;\n\tWD_%=:\n\t}" :: "r"(_m), "r"(_p) : "memory"); \
} while (0)
__device__ __forceinline__ void bulk_cp(uint32_t dst, const void* src, uint32_t bytes, uint32_t mbar) {
    asm volatile(
        "cp.async.bulk.shared::cluster.global.mbarrier::complete_tx::bytes [%0], [%1], %2, [%3];"
        :: "r"(dst), "l"(src), "r"(bytes), "r"(mbar) : "memory");
}

#define LDSM4(R0, R1, R2, R3, A)                                                  \
    asm volatile("ldmatrix.sync.aligned.m8n8.x4.shared.b16 {%0,%1,%2,%3}, [%4];"  \
        : "=r"(R0), "=r"(R1), "=r"(R2), "=r"(R3) : "r"(A))

#define MMA16816(D, A, B0, B1)                                                    \
    asm volatile("mma.sync.aligned.m16n8k16.row.col.f32.f16.f16.f32 "             \
        "{%0,%1,%2,%3}, {%4,%5,%6,%7}, {%8,%9}, {%0,%1,%2,%3};"                   \
        : "+f"((D)[0]), "+f"((D)[1]), "+f"((D)[2]), "+f"((D)[3])                   \
        : "r"((A)[0]), "r"((A)[1]), "r"((A)[2]), "r"((A)[3]), "r"(B0), "r"(B1))

// ---------------- LayerNorm ----------------------------------------------------
__device__ __forceinline__ float block_reduce_sum256(float v, float* red) {
    #pragma unroll
    for (int o = 16; o > 0; o >>= 1) v += __shfl_xor_sync(0xffffffffu, v, o);
    int w = threadIdx.x >> 5;
    if ((threadIdx.x & 31) == 0) red[w] = v;
    __syncthreads();
    float r = (threadIdx.x < 8) ? red[threadIdx.x] : 0.f;
    if (threadIdx.x < 32) {
        #pragma unroll
        for (int o = 4; o > 0; o >>= 1) r += __shfl_xor_sync(0xffffffffu, r, o);
        if (threadIdx.x == 0) red[0] = r;
    }
    __syncthreads();
    float out = red[0];
    __syncthreads();
    return out;
}

__global__ __launch_bounds__(256) void ln_kernel(const float* __restrict__ x,
                                                 const float* __restrict__ b_pre) {
    __shared__ float sx[D_MODEL];
    __shared__ float red[32];
    const int row = blockIdx.x;
    const int t = threadIdx.x;
    const float* xr = x + (size_t)row * D_MODEL;

    float sum = 0.f;
    #pragma unroll
    for (int q = 0; q < 4; q++) { float f = xr[t + q * 256]; sx[t + q * 256] = f; sum += f; }
    float m = block_reduce_sum256(sum, red) * (1.0f / D_MODEL);

    float sq = 0.f;
    #pragma unroll
    for (int q = 0; q < 4; q++) { float c = sx[t + q * 256] - m; sq += c * c; }
    float sd = sqrtf(block_reduce_sum256(sq, red) * (1.0f / (D_MODEL - 1)));
    float inv = 1.0f / (sd + EPS);

    #pragma unroll
    for (int q = 0; q < 4; q++) {
        int col = t + q * 256;
        g_xn[(size_t)row * D_MODEL + col] = (sx[col] - m) * inv - b_pre[col];
    }
    if (t == 0) { g_mu[row] = m; g_sd[row] = sd; }
}

// ---------------- transpose: w_enc -> [D_HID, D_MODEL] fp32 -------------------
__global__ __launch_bounds__(256) void transpose_kernel(const float* __restrict__ w) {
    __shared__ float tile[32][33];
    const int n0 = blockIdx.x * 32, k0 = blockIdx.y * 32;
    const int tx = threadIdx.x, ty = threadIdx.y;
    #pragma unroll
    for (int i = 0; i < 32; i += 8)
        tile[ty + i][tx] = w[(size_t)(k0 + ty + i) * D_HID + n0 + tx];
    __syncthreads();
    #pragma unroll
    for (int i = 0; i < 32; i += 8)
        g_bt[(size_t)(n0 + ty + i) * D_MODEL + k0 + tx] = tile[tx][ty + i];
}

// ---------------- pack: fp32 rows -> pre-swizzled fp16 16KB tiles -------------
// Tile (blk, c): rows blk*128..+127, k = c*64..+63 (scaled by `scale`).
// In-tile offset for (r, e): r*128 + ((e>>3) ^ (r&7))*16 + (e&7)*2  — the exact
// XOR-swizzled smem image, so one contiguous bulk copy lands ready for ldmatrix.
__global__ __launch_bounds__(256) void pack_kernel(const float* __restrict__ src,
                                                   __half* __restrict__ dst,
                                                   float scale) {
    const int blk = blockIdx.x, c = blockIdx.y;
    const int t = threadIdx.x;
    __half* tile = dst + ((size_t)blk * NCHUNK + c) * (TILE_BYTES / 2);
    #pragma unroll
    for (int gi = 0; gi < 4; gi++) {
        const int g = t + gi * 256;           // 16B group id, 0..1023
        const int r = g >> 3, eg = g & 7;
        const float* s = src + (size_t)(blk * 128 + r) * D_MODEL + c * 64 + eg * 8;
        __half2 h[4];
        #pragma unroll
        for (int j = 0; j < 4; j++)
            h[j] = __floats2half2_rn(s[2 * j] * scale, s[2 * j + 1] * scale);
        *reinterpret_cast<uint4*>(
            reinterpret_cast<char*>(tile) + r * 128 + ((eg ^ (r & 7)) * 16)) =
            *reinterpret_cast<uint4*>(h);
    }
}

// ---------------- HMMA GEMM: bulk-copy pipeline -------------------------------
__global__ __launch_bounds__(256, 2) void enc_gemm_mma(const float* __restrict__ bias) {
    extern __shared__ __align__(1024) char smem[];
    const uint32_t sb = smem_u32(smem);
    __shared__ __align__(8) uint64_t mbar_store[2];
    const uint32_t mb0 = smem_u32(&mbar_store[0]);
    const uint32_t mb1 = smem_u32(&mbar_store[1]);

    const int t = threadIdx.x;
    const int wid = t >> 5, lane = t & 31;
    const int wm = wid >> 1, wn = wid & 1;      // 4x2 warps, warp tile 32x64
    const int Mblk = blockIdx.x;                // token tile
    const int Nblk = blockIdx.y;                // hidden tile
    const int bm = Mblk * TM;
    const int bn = Nblk * TN;

    if (t == 0) { MBAR_INIT(mb0, 1); MBAR_INIT(mb1, 1); }
    __syncthreads();

    float acc[2][8][4];
    #pragma unroll
    for (int i = 0; i < 2; i++)
        #pragma unroll
        for (int j = 0; j < 8; j++)
            #pragma unroll
            for (int q = 0; q < 4; q++) acc[i][j][q] = 0.f;

    const int laneA = lane & 15;
    const int hiA   = lane >> 4;
    const int rBoff = (lane & 7) + ((lane >> 4) << 3);
    const int hiB   = (lane >> 3) & 1;

    const char* Abase = (const char*)g_ap + (size_t)Mblk * NCHUNK * TILE_BYTES;
    const char* Bbase = (const char*)g_bp + (size_t)Nblk * NCHUNK * TILE_BYTES;

    // prologue: chunk 0 -> stage 0
    if (t == 0) {
        MBAR_EXPECT(mb0, STAGE_BYTES);
        bulk_cp(sb,         Abase, TILE_BYTES, mb0);
        bulk_cp(sb + 16384, Bbase, TILE_BYTES, mb0);
    }

    for (int c = 0; c < NCHUNK; c++) {
        const int s = c & 1;
        if (c + 1 < NCHUNK && t == 0) {
            const uint32_t mbN = (s ? mb0 : mb1);
            const uint32_t stN = sb + (uint32_t)(1 - s) * STAGE_BYTES;
            MBAR_EXPECT(mbN, STAGE_BYTES);
            bulk_cp(stN,         Abase + (size_t)(c + 1) * TILE_BYTES, TILE_BYTES, mbN);
            bulk_cp(stN + 16384, Bbase + (size_t)(c + 1) * TILE_BYTES, TILE_BYTES, mbN);
        }
        MBAR_WAIT(s ? mb1 : mb0, (c >> 1) & 1);

        const uint32_t base = sb + (uint32_t)s * STAGE_BYTES;
        const uint32_t Ah = base, Bh = base + 16384;

        #pragma unroll
        for (int ks = 0; ks < 4; ks++) {
            const int c0 = ks * 2;
            uint32_t aH[2][4], bH[8][2];
            #pragma unroll
            for (int tm = 0; tm < 2; tm++) {
                int r = wm * 32 + tm * 16 + laneA;
                uint32_t off = (uint32_t)r * 128 + (uint32_t)((((c0 + hiA) ^ (r & 7))) * 16);
                LDSM4(aH[tm][0], aH[tm][1], aH[tm][2], aH[tm][3], Ah + off);
            }
            #pragma unroll
            for (int tp = 0; tp < 4; tp++) {
                int r = wn * 64 + tp * 16 + rBoff;
                uint32_t off = (uint32_t)r * 128 + (uint32_t)((((c0 + hiB) ^ (r & 7))) * 16);
                LDSM4(bH[2*tp][0], bH[2*tp][1], bH[2*tp+1][0], bH[2*tp+1][1], Bh + off);
            }
            #pragma unroll
            for (int tm = 0; tm < 2; tm++)
                #pragma unroll
                for (int tn = 0; tn < 8; tn++)
                    MMA16816(acc[tm][tn], aH[tm], bH[tn][0], bH[tn][1]);
        }
        __syncthreads();   // all readers done with stage s before it is refilled
    }

    // epilogue: unscale (B was x256), add bias, store fp16
    const float inv256 = 1.0f / 256.0f;
    const int gid = lane >> 2, tig = lane & 3;
    #pragma unroll
    for (int tm = 0; tm < 2; tm++) {
        const int r0 = bm + wm * 32 + tm * 16 + gid;
        #pragma unroll
        for (int tn = 0; tn < 8; tn++) {
            const int col = bn + wn * 64 + tn * 8 + tig * 2;
            const float b0 = __ldg(&bias[col]);
            const float b1 = __ldg(&bias[col + 1]);
            __half2 h0 = __floats2half2_rn(acc[tm][tn][0] * inv256 + b0,
                                           acc[tm][tn][1] * inv256 + b1);
            __half2 h1 = __floats2half2_rn(acc[tm][tn][2] * inv256 + b0,
                                           acc[tm][tn][3] * inv256 + b1);
            *reinterpret_cast<__half2*>(&g_preh[(size_t)r0 * D_HID + col]) = h0;
            *reinterpret_cast<__half2*>(&g_preh[(size_t)(r0 + 8) * D_HID + col]) = h1;
        }
    }
}

// ---------------- topk: fp16-key histogram select + candidate collection ------
__device__ __forceinline__ int bin_of_half_bits(uint32_t h) {
    uint32_t k = (h & 0x8000u) ? ((~h) & 0xFFFFu) : (h | 0x8000u);
    return (int)(k >> 4);
}

__global__ __launch_bounds__(256) void topk_kernel() {
    __shared__ int hist[NBINS];            // 16 KB
    __shared__ int segs[256];
    __shared__ int warpTot[8];
    __shared__ float s_thr;
    __shared__ int s_cnt;

    const int row = blockIdx.x;
    const int t = threadIdx.x;
    const int lane = t & 31, wid = t >> 5;
    const uint4* p4 = reinterpret_cast<const uint4*>(g_preh + (size_t)row * D_HID);

    #pragma unroll
    for (int i = 0; i < NBINS / 256; i++) hist[t + i * 256] = 0;
    if (t == 0) s_cnt = 0;
    __syncthreads();

    #pragma unroll
    for (int i = 0; i < D_HID / 8 / 256; i++) {
        uint4 v = p4[t + i * 256];
        atomicAdd(&hist[bin_of_half_bits(v.x & 0xFFFFu)], 1);
        atomicAdd(&hist[bin_of_half_bits(v.x >> 16)], 1);
        atomicAdd(&hist[bin_of_half_bits(v.y & 0xFFFFu)], 1);
        atomicAdd(&hist[bin_of_half_bits(v.y >> 16)], 1);
        atomicAdd(&hist[bin_of_half_bits(v.z & 0xFFFFu)], 1);
        atomicAdd(&hist[bin_of_half_bits(v.z >> 16)], 1);
        atomicAdd(&hist[bin_of_half_bits(v.w & 0xFFFFu)], 1);
        atomicAdd(&hist[bin_of_half_bits(v.w >> 16)], 1);
    }
    __syncthreads();

    int seg = 0;
    #pragma unroll
    for (int k = 0; k < 16; k++) seg += hist[t * 16 + k];
    segs[t] = seg;
    int wsum = seg;
    #pragma unroll
    for (int o = 16; o > 0; o >>= 1) wsum += __shfl_xor_sync(0xffffffffu, wsum, o);
    if (lane == 0) warpTot[wid] = wsum;
    __syncthreads();

    if (t == 0) {
        int cum = 0, w = 7;
        for (; w > 0; w--) { if (cum + warpTot[w] >= TOPK) break; cum += warpTot[w]; }
        int s = w * 32 + 31;
        for (; s > w * 32; s--) { if (cum + segs[s] >= TOPK) break; cum += segs[s]; }
        int b = s * 16 + 15;
        for (; b > s * 16; b--) { if (cum + hist[b] >= TOPK) break; cum += hist[b]; }
        uint32_t keyLo = (uint32_t)b << 4;
        uint32_t hbits = (keyLo & 0x8000u) ? (keyLo & 0x7FFFu) : ((~keyLo) & 0xFFFFu);
        __half_raw hr; hr.x = (unsigned short)hbits;
        s_thr = __half2float(__half(hr)) - MARGIN;
    }
    __syncthreads();

    const float thr = s_thr;
    const __half* p = g_preh + (size_t)row * D_HID;
    for (int i = t; i < D_HID; i += 256) {
        if (__half2float(p[i]) >= thr) {
            int pos = atomicAdd(&s_cnt, 1);
            if (pos < CAND_MAX) g_ci[(size_t)row * CAND_MAX + pos] = i;
        }
    }
    __syncthreads();
    if (t == 0) g_cn[row] = (s_cnt < CAND_MAX) ? s_cnt : CAND_MAX;
}

// ---------------- rescue: exact fp32 dots (R1-identical order) + top-128 ------
__global__ __launch_bounds__(256, 2) void rescue_kernel(const float* __restrict__ b_enc) {
    extern __shared__ float dyn[];
    float* sx = dyn;                                   // [D_MODEL]
    float* sw = dyn + D_MODEL;                         // [CAND_MAX][RPAD]
    float* sv = sw + CAND_MAX * RPAD;                  // [CAND_MAX]
    int*   si = (int*)(sv + CAND_MAX);                 // [CAND_MAX]

    const int row = blockIdx.x;
    const int t = threadIdx.x;

    #pragma unroll
    for (int q = 0; q < 4; q++)
        sx[t + q * 256] = g_xn[(size_t)row * D_MODEL + t + q * 256];
    si[t] = (t < g_cn[row]) ? g_ci[(size_t)row * CAND_MAX + t] : 0x7FFFFFFF;
    __syncthreads();
    const int C = g_cn[row];
    const int myIdx = si[t];

    float acc = 0.f;
    for (int k0 = 0; k0 < D_MODEL; k0 += RTILE) {
        const int q = t & 15;                // 16 float4 = 64 floats
        #pragma unroll
        for (int pass = 0; pass < 16; pass++) {
            const int c = pass * 16 + (t >> 4);
            if (c < C) {
                const float4 v = *reinterpret_cast<const float4*>(
                    g_bt + (size_t)si[c] * D_MODEL + k0 + q * 4);
                float* dst = sw + c * RPAD + q * 4;
                dst[0] = v.x; dst[1] = v.y; dst[2] = v.z; dst[3] = v.w;
            }
        }
        __syncthreads();
        if (t < C) {
            const float* wrow = sw + t * RPAD;
            #pragma unroll
            for (int kk = 0; kk < RTILE; kk++)
                acc = fmaf(sx[k0 + kk], wrow[kk], acc);   // strict sequential chain
        }
        __syncthreads();
    }

    if (t < C) {
        sv[t] = acc + __ldg(&b_enc[myIdx]);
    } else {
        sv[t] = -__int_as_float(0x7F800000);   // -inf
    }
    __syncthreads();

    // bitonic sort 256: val desc, idx asc (jax tie order)
    #pragma unroll 1
    for (int k = 2; k <= CAND_MAX; k <<= 1) {
        #pragma unroll 1
        for (int j = k >> 1; j > 0; j >>= 1) {
            const int ixj = t ^ j;
            if (ixj > t) {
                float v0 = sv[t], v1 = sv[ixj];
                int i0 = si[t], i1 = si[ixj];
                bool firstWins = (v0 > v1) || (v0 == v1 && i0 < i1);
                if (((t & k) == 0) != firstWins) {
                    sv[t] = v1; sv[ixj] = v0;
                    si[t] = i1; si[ixj] = i0;
                }
            }
            __syncthreads();
        }
    }

    if (t < TOPK) {
        g_tv[(size_t)row * TOPK + t] = fmaxf(sv[t], 0.0f);
        g_ti[(size_t)row * TOPK + t] = si[t];
    }
}

// ---------------- sparse decode + de-normalize -------------------------------
__global__ __launch_bounds__(256) void decode_kernel(const float* __restrict__ w_dec,
                                                     const float* __restrict__ b_pre,
                                                     float* __restrict__ out) {
    __shared__ float sval[TOPK];
    __shared__ int   sidx[TOPK];
    const int row = blockIdx.x;
    const int t = threadIdx.x;
    if (t < TOPK) {
        sval[t] = g_tv[(size_t)row * TOPK + t];
        sidx[t] = g_ti[(size_t)row * TOPK + t];
    }
    __syncthreads();

    float acc0 = 0.f, acc1 = 0.f, acc2 = 0.f, acc3 = 0.f;
    #pragma unroll 4
    for (int j = 0; j < TOPK; j++) {
        const float v = sval[j];
        const float* wr = w_dec + (size_t)sidx[j] * D_MODEL;
        acc0 += v * __ldg(&wr[t]);
        acc1 += v * __ldg(&wr[t + 256]);
        acc2 += v * __ldg(&wr[t + 512]);
        acc3 += v * __ldg(&wr[t + 768]);
    }
    const float m = g_mu[row], s = g_sd[row];
    float* o = out + (size_t)row * D_MODEL;
    o[t]       = (acc0 + b_pre[t])       * s + m;
    o[t + 256] = (acc1 + b_pre[t + 256]) * s + m;
    o[t + 512] = (acc2 + b_pre[t + 512]) * s + m;
    o[t + 768] = (acc3 + b_pre[t + 768]) * s + m;
}

// ---------------- launch ------------------------------------------------------
extern "C" void kernel_launch(void* const* d_in, const int* in_sizes, int n_in,
                              void* d_out, int out_size) {
    const float* x     = (const float*)d_in[0];
    const float* w_enc = (const float*)d_in[1];
    const float* w_dec = (const float*)d_in[2];
    const float* b_enc = (const float*)d_in[3];
    const float* b_pre = (const float*)d_in[4];
    float* out = (float*)d_out;

    float* d_xn; cudaGetSymbolAddress((void**)&d_xn, g_xn);
    float* d_bt; cudaGetSymbolAddress((void**)&d_bt, g_bt);
    __half* d_ap; cudaGetSymbolAddress((void**)&d_ap, g_ap);
    __half* d_bp; cudaGetSymbolAddress((void**)&d_bp, g_bp);

    // 1. LayerNorm (fp32 out)
    ln_kernel<<<N_TOK, 256>>>(x, b_pre);

    // 2. Transpose w_enc -> fp32 [D_HID, D_MODEL]
    dim3 tg(D_HID / 32, D_MODEL / 32);
    transpose_kernel<<<tg, dim3(32, 8)>>>(w_enc);

    // 3. Pack fp32 -> pre-swizzled fp16 16KB tiles (A x1, B x256)
    pack_kernel<<<dim3(N_TOK / 128, NCHUNK), 256>>>(d_xn, d_ap, 1.0f);
    pack_kernel<<<dim3(D_HID / 128, NCHUNK), 256>>>(d_bt, d_bp, 256.0f);

    // 4. HMMA encoder GEMM with cp.async.bulk pipeline (2 bulk ops per chunk)
    cudaFuncSetAttribute(enc_gemm_mma, cudaFuncAttributeMaxDynamicSharedMemorySize, GEMM_SMEM);
    dim3 ggrid(N_TOK / TM, D_HID / TN);
    enc_gemm_mma<<<ggrid, 256, GEMM_SMEM>>>(b_enc);

    // 5. Histogram-select approx top-128 + margin candidate collection
    topk_kernel<<<N_TOK, 256>>>();

    // 6. Rescue: R1-identical sequential fp32 dots, smem-staged coalesced loads
    cudaFuncSetAttribute(rescue_kernel, cudaFuncAttributeMaxDynamicSharedMemorySize, RES_SMEM);
    rescue_kernel<<<N_TOK, 256, RES_SMEM>>>(b_enc);

    // 7. Sparse decode + un-normalize
    decode_kernel<<<N_TOK, 256>>>(w_dec, b_pre, out);
}